// round 2
// baseline (speedup 1.0000x reference)
#include <cuda_runtime.h>
#include <math.h>

#define B_   4
#define A_   2048
#define D_   512
#define H_   4
#define HD_  128
#define M_   (B_*A_)     // 8192 rows
#define NBH  (B_*H_)     // 16 batch-heads
#define EPSL 1e-5f
#define SCALE 0.08838834764831845f  // 1/sqrt(128)

// ---------------- scratch (static device globals; no runtime allocation) ----
__device__ float g_xn[M_*D_];                 // xn, later reused as attn output
__device__ float g_q [M_*D_];
__device__ float g_k [M_*D_];
__device__ float g_v [M_*D_];
__device__ float g_t1[M_*D_];
__device__ float g_t2[M_*D_];
__device__ float g_s [(size_t)NBH*A_*A_];     // 268 MB scores/probs
__device__ int   g_connfmt;                   // 0=int32, 1=uint8, 2=float32

// ---------------- connectivity format detection -----------------------------
// Scans first B*A*A bytes (safe under every candidate dtype).
// bit0: nonzero byte found at offset%4 != 0
// bit1: byte value > 1 found
__global__ void detect_kernel(const unsigned char* __restrict__ c)
{
    size_t n = (size_t)B_ * A_ * A_;    // 16 MB
    int found = 0;
    for (size_t i = (size_t)blockIdx.x * blockDim.x + threadIdx.x;
         i < n; i += (size_t)gridDim.x * blockDim.x) {
        unsigned char v = c[i];
        if (v) {
            if ((i & 3) != 0) found |= 1;
            if (v > 1)        found |= 2;
        }
    }
    #pragma unroll
    for (int o = 16; o; o >>= 1) found |= __shfl_xor_sync(0xffffffffu, found, o);
    if ((threadIdx.x & 31) == 0 && found) atomicOr(&g_connfmt, found);
}

__global__ void resolve_fmt_kernel()
{
    // bits -> format: 0 => int32 ; bit0 only => uint8 ; bit0|bit1 => float32
    int bits = g_connfmt;
    int fmt;
    if ((bits & 1) == 0)      fmt = 0;   // int32 0/1
    else if ((bits & 2) == 0) fmt = 1;   // uint8 0/1
    else                      fmt = 2;   // float32 0.0/1.0
    g_connfmt = fmt;
}

__device__ __forceinline__ bool conn_at(const void* cn, size_t idx, int fmt)
{
    if (fmt == 0) return ((const int*)cn)[idx] != 0;
    if (fmt == 1) return ((const unsigned char*)cn)[idx] != 0;
    return ((const float*)cn)[idx] != 0.0f;
}

// ---------------- LayerNorm (optionally preceded by Swish) ------------------
// one block (128 threads) per row of 512 floats
template<bool SWISH>
__global__ void ln_kernel(const float* __restrict__ in, float* __restrict__ out,
                          const float* __restrict__ w, const float* __restrict__ bb)
{
    __shared__ float red[8];
    int row = blockIdx.x;
    int t = threadIdx.x;                       // 0..127
    const float4* x4 = (const float4*)(in + (size_t)row * D_);
    float4 v = x4[t];
    if (SWISH) {
        v.x *= 1.f/(1.f+__expf(-v.x));
        v.y *= 1.f/(1.f+__expf(-v.y));
        v.z *= 1.f/(1.f+__expf(-v.z));
        v.w *= 1.f/(1.f+__expf(-v.w));
    }
    int warp = t >> 5, lane = t & 31;
    float s = v.x + v.y + v.z + v.w;
    #pragma unroll
    for (int o = 16; o; o >>= 1) s += __shfl_xor_sync(0xffffffffu, s, o);
    if (lane == 0) red[warp] = s;
    __syncthreads();
    float mu = (red[0]+red[1]+red[2]+red[3]) * (1.f/D_);
    float dx = v.x-mu, dy = v.y-mu, dz = v.z-mu, dw = v.w-mu;
    float q = dx*dx + dy*dy + dz*dz + dw*dw;
    #pragma unroll
    for (int o = 16; o; o >>= 1) q += __shfl_xor_sync(0xffffffffu, q, o);
    if (lane == 0) red[4+warp] = q;
    __syncthreads();
    float var = (red[4]+red[5]+red[6]+red[7]) * (1.f/D_);
    float r = rsqrtf(var + EPSL);
    float4 wv = ((const float4*)w)[t];
    float4 bv = ((const float4*)bb)[t];
    float4 o4;
    o4.x = dx*r*wv.x + bv.x;
    o4.y = dy*r*wv.y + bv.y;
    o4.z = dz*r*wv.z + bv.z;
    o4.w = dw*r*wv.w + bv.w;
    ((float4*)(out + (size_t)row * D_))[t] = o4;
}

// ---------------- NT GEMM: C[m,n] = sum_k A[m,k]*B[n,k] (+bias) -------------
// 64x64 tile, BK=16, 256 threads, 4x4 per thread
__global__ void gemm_nt(const float* __restrict__ A, int lda,
                        const float* __restrict__ Bm, int ldb,
                        float* __restrict__ C, int ldc,
                        int K, const float* __restrict__ bias)
{
    __shared__ float As[16][65];
    __shared__ float Bs[16][65];
    int t  = threadIdx.x;
    int tx = t & 15, ty = t >> 4;
    int m0 = blockIdx.y << 6, n0 = blockIdx.x << 6;
    int lrow = t >> 2;            // 0..63
    int lk   = (t & 3) << 2;      // 0,4,8,12
    const float* Ap = A  + (size_t)(m0 + lrow) * lda + lk;
    const float* Bp = Bm + (size_t)(n0 + lrow) * ldb + lk;
    float acc[4][4] = {};
    for (int k0 = 0; k0 < K; k0 += 16) {
        float4 av = *(const float4*)(Ap + k0);
        float4 bv = *(const float4*)(Bp + k0);
        __syncthreads();
        As[lk+0][lrow]=av.x; As[lk+1][lrow]=av.y; As[lk+2][lrow]=av.z; As[lk+3][lrow]=av.w;
        Bs[lk+0][lrow]=bv.x; Bs[lk+1][lrow]=bv.y; Bs[lk+2][lrow]=bv.z; Bs[lk+3][lrow]=bv.w;
        __syncthreads();
        #pragma unroll
        for (int kk = 0; kk < 16; kk++) {
            float a[4], b[4];
            #pragma unroll
            for (int i = 0; i < 4; i++) a[i] = As[kk][(ty<<2)+i];
            #pragma unroll
            for (int j = 0; j < 4; j++) b[j] = Bs[kk][(tx<<2)+j];
            #pragma unroll
            for (int i = 0; i < 4; i++)
                #pragma unroll
                for (int j = 0; j < 4; j++)
                    acc[i][j] += a[i] * b[j];
        }
    }
    #pragma unroll
    for (int i = 0; i < 4; i++) {
        float* Cp = C + (size_t)(m0 + (ty<<2) + i) * ldc + n0 + (tx<<2);
        #pragma unroll
        for (int j = 0; j < 4; j++) {
            float vv = acc[i][j];
            if (bias) vv += bias[n0 + (tx<<2) + j];
            Cp[j] = vv;
        }
    }
}

// ---------------- scores: S = mask(Q K^T * scale) ---------------------------
__global__ void scores_kernel(const float* __restrict__ Q,
                              const float* __restrict__ Kc,
                              const void* __restrict__ conn,
                              float* __restrict__ S)
{
    int bh = blockIdx.z;
    int b = bh >> 2, h = bh & 3;
    const float* A  = Q  + (size_t)b * A_ * D_ + h * HD_;
    const float* Bm = Kc + (size_t)b * A_ * D_ + h * HD_;
    float* C = S + (size_t)bh * A_ * A_;
    size_t cbase = (size_t)b * A_ * A_;
    int fmt = g_connfmt;

    __shared__ float As[16][65];
    __shared__ float Bs[16][65];
    int t  = threadIdx.x;
    int tx = t & 15, ty = t >> 4;
    int m0 = blockIdx.y << 6, n0 = blockIdx.x << 6;
    int lrow = t >> 2;
    int lk   = (t & 3) << 2;
    const float* Ap = A  + (size_t)(m0 + lrow) * D_ + lk;
    const float* Bp = Bm + (size_t)(n0 + lrow) * D_ + lk;
    float acc[4][4] = {};
    for (int k0 = 0; k0 < HD_; k0 += 16) {
        float4 av = *(const float4*)(Ap + k0);
        float4 bv = *(const float4*)(Bp + k0);
        __syncthreads();
        As[lk+0][lrow]=av.x; As[lk+1][lrow]=av.y; As[lk+2][lrow]=av.z; As[lk+3][lrow]=av.w;
        Bs[lk+0][lrow]=bv.x; Bs[lk+1][lrow]=bv.y; Bs[lk+2][lrow]=bv.z; Bs[lk+3][lrow]=bv.w;
        __syncthreads();
        #pragma unroll
        for (int kk = 0; kk < 16; kk++) {
            float a[4], b[4];
            #pragma unroll
            for (int i = 0; i < 4; i++) a[i] = As[kk][(ty<<2)+i];
            #pragma unroll
            for (int j = 0; j < 4; j++) b[j] = Bs[kk][(tx<<2)+j];
            #pragma unroll
            for (int i = 0; i < 4; i++)
                #pragma unroll
                for (int j = 0; j < 4; j++)
                    acc[i][j] += a[i] * b[j];
        }
    }
    #pragma unroll
    for (int i = 0; i < 4; i++) {
        int qrow = m0 + (ty<<2) + i;
        #pragma unroll
        for (int j = 0; j < 4; j++) {
            int kcol = n0 + (tx<<2) + j;
            bool on = conn_at(conn, cbase + (size_t)qrow * A_ + kcol, fmt);
            C[(size_t)qrow * A_ + kcol] = on ? acc[i][j] * SCALE : -INFINITY;
        }
    }
}

// ---------------- softmax over rows of S (in place) -------------------------
// one block (256 threads) per row of 2048
__global__ void softmax_kernel(float* __restrict__ S)
{
    __shared__ float redm[8];
    __shared__ float reds[8];
    float* p = S + (size_t)blockIdx.x * A_;
    int t = threadIdx.x;                    // 0..255
    int warp = t >> 5, lane = t & 31;
    float4 v0 = ((float4*)p)[t];
    float4 v1 = ((float4*)p)[t + 256];
    float m = fmaxf(fmaxf(fmaxf(v0.x,v0.y),fmaxf(v0.z,v0.w)),
                    fmaxf(fmaxf(v1.x,v1.y),fmaxf(v1.z,v1.w)));
    #pragma unroll
    for (int o = 16; o; o >>= 1) m = fmaxf(m, __shfl_xor_sync(0xffffffffu, m, o));
    if (lane == 0) redm[warp] = m;
    __syncthreads();
    float mm = redm[0];
    #pragma unroll
    for (int i = 1; i < 8; i++) mm = fmaxf(mm, redm[i]);

    #define EX(x) ((x) <= -1e30f ? 0.f : __expf((x) - mm))
    v0.x = EX(v0.x); v0.y = EX(v0.y); v0.z = EX(v0.z); v0.w = EX(v0.w);
    v1.x = EX(v1.x); v1.y = EX(v1.y); v1.z = EX(v1.z); v1.w = EX(v1.w);
    #undef EX
    float s = v0.x+v0.y+v0.z+v0.w + v1.x+v1.y+v1.z+v1.w;
    #pragma unroll
    for (int o = 16; o; o >>= 1) s += __shfl_xor_sync(0xffffffffu, s, o);
    if (lane == 0) reds[warp] = s;
    __syncthreads();
    float tot = reds[0];
    #pragma unroll
    for (int i = 1; i < 8; i++) tot += reds[i];
    float inv = 1.f / tot;
    v0.x*=inv; v0.y*=inv; v0.z*=inv; v0.w*=inv;
    v1.x*=inv; v1.y*=inv; v1.z*=inv; v1.w*=inv;
    ((float4*)p)[t]       = v0;
    ((float4*)p)[t + 256] = v1;
}

// ---------------- PV: O = P @ V (NN GEMM) -----------------------------------
__global__ void pv_kernel(const float* __restrict__ S, const float* __restrict__ V,
                          float* __restrict__ O)
{
    int bh = blockIdx.z;
    int b = bh >> 2, h = bh & 3;
    const float* A  = S + (size_t)bh * A_ * A_;              // lda = A_
    const float* Bm = V + (size_t)b * A_ * D_ + h * HD_;     // ldb = D_
    float* C        = O + (size_t)b * A_ * D_ + h * HD_;     // ldc = D_

    __shared__ float As[16][65];
    __shared__ float Bs[16][65];
    int t  = threadIdx.x;
    int tx = t & 15, ty = t >> 4;
    int m0 = blockIdx.y << 6, n0 = blockIdx.x << 6;
    int lrow = t >> 2;            // A loader
    int lk   = (t & 3) << 2;
    int bk   = t >> 4;            // B loader: row in K-tile
    int bn   = (t & 15) << 2;     // col
    float acc[4][4] = {};
    for (int k0 = 0; k0 < A_; k0 += 16) {
        float4 av = *(const float4*)(A  + (size_t)(m0 + lrow) * A_ + k0 + lk);
        float4 bv = *(const float4*)(Bm + (size_t)(k0 + bk) * D_ + n0 + bn);
        __syncthreads();
        As[lk+0][lrow]=av.x; As[lk+1][lrow]=av.y; As[lk+2][lrow]=av.z; As[lk+3][lrow]=av.w;
        Bs[bk][bn+0]=bv.x; Bs[bk][bn+1]=bv.y; Bs[bk][bn+2]=bv.z; Bs[bk][bn+3]=bv.w;
        __syncthreads();
        #pragma unroll
        for (int kk = 0; kk < 16; kk++) {
            float a[4], b[4];
            #pragma unroll
            for (int i = 0; i < 4; i++) a[i] = As[kk][(ty<<2)+i];
            #pragma unroll
            for (int j = 0; j < 4; j++) b[j] = Bs[kk][(tx<<2)+j];
            #pragma unroll
            for (int i = 0; i < 4; i++)
                #pragma unroll
                for (int j = 0; j < 4; j++)
                    acc[i][j] += a[i] * b[j];
        }
    }
    #pragma unroll
    for (int i = 0; i < 4; i++) {
        float* Cp = C + (size_t)(m0 + (ty<<2) + i) * D_ + n0 + (tx<<2);
        #pragma unroll
        for (int j = 0; j < 4; j++) Cp[j] = acc[i][j];
    }
}

// ---------------- launcher --------------------------------------------------
extern "C" void kernel_launch(void* const* d_in, const int* in_sizes, int n_in,
                              void* d_out, int out_size)
{
    const float*         x      = (const float*)d_in[0];
    const void*          conn   = (const void*)d_in[1];
    const float*         Wq     = (const float*)d_in[2];
    const float*         Wk     = (const float*)d_in[3];
    const float*         Wv     = (const float*)d_in[4];
    const float*         norm_w = (const float*)d_in[5];
    const float*         norm_b = (const float*)d_in[6];
    const float*         ln1_w  = (const float*)d_in[7];
    const float*         ln1_b  = (const float*)d_in[8];
    const float*         fc1_w  = (const float*)d_in[9];
    const float*         fc1_b  = (const float*)d_in[10];
    const float*         ln2_w  = (const float*)d_in[11];
    const float*         ln2_b  = (const float*)d_in[12];
    const float*         fc2_w  = (const float*)d_in[13];
    const float*         fc2_b  = (const float*)d_in[14];
    float* out = (float*)d_out;

    float *p_xn, *p_q, *p_k, *p_v, *p_t1, *p_t2, *p_s;
    int* p_fmt;
    cudaGetSymbolAddress((void**)&p_xn, g_xn);
    cudaGetSymbolAddress((void**)&p_q,  g_q);
    cudaGetSymbolAddress((void**)&p_k,  g_k);
    cudaGetSymbolAddress((void**)&p_v,  g_v);
    cudaGetSymbolAddress((void**)&p_t1, g_t1);
    cudaGetSymbolAddress((void**)&p_t2, g_t2);
    cudaGetSymbolAddress((void**)&p_s,  g_s);
    cudaGetSymbolAddress((void**)&p_fmt, g_connfmt);

    // 0. detect connectivity dtype (deterministic w.r.t. input)
    cudaMemsetAsync(p_fmt, 0, sizeof(int));
    detect_kernel<<<256, 256>>>((const unsigned char*)conn);
    resolve_fmt_kernel<<<1, 1>>>();

    // 1. xn = LN(x)
    ln_kernel<false><<<M_, 128>>>(x, p_xn, norm_w, norm_b);

    // 2. Q, K, V
    dim3 gemm_grid(D_/64, M_/64);
    gemm_nt<<<gemm_grid, 256>>>(p_xn, D_, Wq, D_, p_q, D_, D_, nullptr);
    gemm_nt<<<gemm_grid, 256>>>(p_xn, D_, Wk, D_, p_k, D_, D_, nullptr);
    gemm_nt<<<gemm_grid, 256>>>(p_xn, D_, Wv, D_, p_v, D_, D_, nullptr);

    // 3. scores + mask
    scores_kernel<<<dim3(A_/64, A_/64, NBH), 256>>>(p_q, p_k, conn, p_s);

    // 4. softmax
    softmax_kernel<<<NBH * A_, 256>>>(p_s);

    // 5. O = P @ V  (reuse g_xn as attention output)
    pv_kernel<<<dim3(HD_/64, A_/64, NBH), 256>>>(p_s, p_v, p_xn);

    // 6. t1 = LN(swish(O)); h1 = t1 @ fc1^T + b1
    ln_kernel<true><<<M_, 128>>>(p_xn, p_t1, ln1_w, ln1_b);
    gemm_nt<<<gemm_grid, 256>>>(p_t1, D_, fc1_w, D_, p_t2, D_, D_, fc1_b);

    // 7. t1 = LN(swish(h1)); h2 = t1 @ fc2^T + b2
    ln_kernel<true><<<M_, 128>>>(p_t2, p_t1, ln2_w, ln2_b);
    gemm_nt<<<gemm_grid, 256>>>(p_t1, D_, fc2_w, D_, p_t2, D_, D_, fc2_b);

    // 8. out = LN(h2)
    ln_kernel<false><<<M_, 128>>>(p_t2, out, norm_w, norm_b);
}

// round 3
// speedup vs baseline: 2.9389x; 2.9389x over previous
#include <cuda_runtime.h>
#include <math.h>
#include <stdint.h>

#define B_   4
#define A_   2048
#define D_   512
#define H_   4
#define HD_  128
#define M_   (B_*A_)     // 8192 rows
#define NBH  (B_*H_)     // 16 batch-heads
#define EPSL 1e-5f
#define SCALE 0.08838834764831845f  // 1/sqrt(128)

// ---------------- scratch -----------------------------------------------------
__device__ float g_xn[M_*D_];
__device__ float g_q [M_*D_];
__device__ float g_k [M_*D_];
__device__ float g_v [M_*D_];
__device__ float g_t1[M_*D_];
__device__ float g_t2[M_*D_];
__device__ float g_s [(size_t)NBH*A_*A_];
__device__ int   g_connfmt;

// ---------------- connectivity format detection -------------------------------
__global__ void detect_kernel(const unsigned char* __restrict__ c)
{
    size_t n = (size_t)B_ * A_ * A_;
    int found = 0;
    for (size_t i = (size_t)blockIdx.x * blockDim.x + threadIdx.x;
         i < n; i += (size_t)gridDim.x * blockDim.x) {
        unsigned char v = c[i];
        if (v) {
            if ((i & 3) != 0) found |= 1;
            if (v > 1)        found |= 2;
        }
    }
    #pragma unroll
    for (int o = 16; o; o >>= 1) found |= __shfl_xor_sync(0xffffffffu, found, o);
    if ((threadIdx.x & 31) == 0 && found) atomicOr(&g_connfmt, found);
}

__global__ void resolve_fmt_kernel()
{
    int bits = g_connfmt;
    int fmt;
    if ((bits & 1) == 0)      fmt = 0;   // int32
    else if ((bits & 2) == 0) fmt = 1;   // uint8
    else                      fmt = 2;   // float32
    g_connfmt = fmt;
}

__device__ __forceinline__ bool conn_at(const void* cn, size_t idx, int fmt)
{
    if (fmt == 0) return ((const int*)cn)[idx] != 0;
    if (fmt == 1) return ((const unsigned char*)cn)[idx] != 0;
    return ((const float*)cn)[idx] != 0.0f;
}

// ---------------- tf32 helpers -------------------------------------------------
__device__ __forceinline__ uint32_t f2tf(float x)
{
    uint32_t r;
    asm("cvt.rna.tf32.f32 %0, %1;" : "=r"(r) : "f"(x));
    return r;
}
__device__ __forceinline__ uint4 cvt4(float4 v)
{
    uint4 u;
    u.x = f2tf(v.x); u.y = f2tf(v.y); u.z = f2tf(v.z); u.w = f2tf(v.w);
    return u;
}

#define MMA8(d, a, b) asm volatile( \
  "mma.sync.aligned.m16n8k8.row.col.f32.tf32.tf32.f32 " \
  "{%0,%1,%2,%3},{%4,%5,%6,%7},{%8,%9},{%0,%1,%2,%3};" \
  : "+f"(d[0]), "+f"(d[1]), "+f"(d[2]), "+f"(d[3]) \
  : "r"(a[0]), "r"(a[1]), "r"(a[2]), "r"(a[3]), "r"(b[0]), "r"(b[1]))

// ---------------- LayerNorm (optional Swish) -----------------------------------
template<bool SWISH>
__global__ void ln_kernel(const float* __restrict__ in, float* __restrict__ out,
                          const float* __restrict__ w, const float* __restrict__ bb)
{
    __shared__ float red[8];
    int row = blockIdx.x;
    int t = threadIdx.x;
    const float4* x4 = (const float4*)(in + (size_t)row * D_);
    float4 v = x4[t];
    if (SWISH) {
        v.x *= 1.f/(1.f+__expf(-v.x));
        v.y *= 1.f/(1.f+__expf(-v.y));
        v.z *= 1.f/(1.f+__expf(-v.z));
        v.w *= 1.f/(1.f+__expf(-v.w));
    }
    int warp = t >> 5, lane = t & 31;
    float s = v.x + v.y + v.z + v.w;
    #pragma unroll
    for (int o = 16; o; o >>= 1) s += __shfl_xor_sync(0xffffffffu, s, o);
    if (lane == 0) red[warp] = s;
    __syncthreads();
    float mu = (red[0]+red[1]+red[2]+red[3]) * (1.f/D_);
    float dx = v.x-mu, dy = v.y-mu, dz = v.z-mu, dw = v.w-mu;
    float q = dx*dx + dy*dy + dz*dz + dw*dw;
    #pragma unroll
    for (int o = 16; o; o >>= 1) q += __shfl_xor_sync(0xffffffffu, q, o);
    if (lane == 0) red[4+warp] = q;
    __syncthreads();
    float var = (red[4]+red[5]+red[6]+red[7]) * (1.f/D_);
    float r = rsqrtf(var + EPSL);
    float4 wv = ((const float4*)w)[t];
    float4 bv = ((const float4*)bb)[t];
    float4 o4;
    o4.x = dx*r*wv.x + bv.x;
    o4.y = dy*r*wv.y + bv.y;
    o4.z = dz*r*wv.z + bv.z;
    o4.w = dw*r*wv.w + bv.w;
    ((float4*)(out + (size_t)row * D_))[t] = o4;
}

// ===============================================================================
// tf32 mma NT GEMM: C[m,n] = sum_k A[m,k] * B[n,k]  (+bias)
// 128x128 block tile, BK=16, 256 threads (8 warps, 2Mx4N), m16n8k8 tf32.
// Smem: As/Bs stored [row][k] with stride 20 (conflict-free, float4-alignable).
// ===============================================================================
__global__ __launch_bounds__(256, 2)
void mma_nt(const float* __restrict__ A, int lda,
            const float* __restrict__ Bm, int ldb,
            float* __restrict__ C, int ldc, int K,
            const float* __restrict__ bias)
{
    __shared__ uint32_t As[2][128*20];
    __shared__ uint32_t Bs[2][128*20];
    int t = threadIdx.x;
    int m0 = blockIdx.y << 7, n0 = blockIdx.x << 7;
    int warp = t >> 5, lane = t & 31, g = lane >> 2, tg = lane & 3;
    int wm = (warp & 1) << 6;        // 0 / 64
    int wn = (warp >> 1) << 5;       // 0 / 32 / 64 / 96
    float acc[4][4][4] = {};

    int ra0 = t >> 2,        ca0 = (t & 3) << 2;          // float4 #0
    int ra1 = (t + 256) >> 2, ca1 = (t & 3) << 2;         // float4 #1 (same col pattern)
    const float* Ap0 = A  + (size_t)(m0 + ra0) * lda + ca0;
    const float* Ap1 = A  + (size_t)(m0 + ra1) * lda + ca1;
    const float* Bp0 = Bm + (size_t)(n0 + ra0) * ldb + ca0;
    const float* Bp1 = Bm + (size_t)(n0 + ra1) * ldb + ca1;

    float4 pa0, pa1, pb0, pb1;
    int KT = K >> 4;

    pa0 = *(const float4*)(Ap0); pa1 = *(const float4*)(Ap1);
    pb0 = *(const float4*)(Bp0); pb1 = *(const float4*)(Bp1);
    *(uint4*)(&As[0][ra0*20 + ca0]) = cvt4(pa0);
    *(uint4*)(&As[0][ra1*20 + ca1]) = cvt4(pa1);
    *(uint4*)(&Bs[0][ra0*20 + ca0]) = cvt4(pb0);
    *(uint4*)(&Bs[0][ra1*20 + ca1]) = cvt4(pb1);
    __syncthreads();

    for (int kt = 0; kt < KT; kt++) {
        if (kt + 1 < KT) {
            int k0 = (kt + 1) << 4;
            pa0 = *(const float4*)(Ap0 + k0); pa1 = *(const float4*)(Ap1 + k0);
            pb0 = *(const float4*)(Bp0 + k0); pb1 = *(const float4*)(Bp1 + k0);
        }
        const uint32_t* as = As[kt & 1];
        const uint32_t* bs = Bs[kt & 1];
        #pragma unroll
        for (int ks = 0; ks < 2; ks++) {
            int kb = ks << 3;
            uint32_t af[4][4], bf[4][2];
            #pragma unroll
            for (int i = 0; i < 4; i++) {
                int r = wm + (i << 4) + g;
                af[i][0] = as[r*20 + kb + tg];
                af[i][1] = as[(r+8)*20 + kb + tg];
                af[i][2] = as[r*20 + kb + tg + 4];
                af[i][3] = as[(r+8)*20 + kb + tg + 4];
            }
            #pragma unroll
            for (int j = 0; j < 4; j++) {
                int n = wn + (j << 3) + g;
                bf[j][0] = bs[n*20 + kb + tg];
                bf[j][1] = bs[n*20 + kb + tg + 4];
            }
            #pragma unroll
            for (int i = 0; i < 4; i++)
                #pragma unroll
                for (int j = 0; j < 4; j++)
                    MMA8(acc[i][j], af[i], bf[j]);
        }
        if (kt + 1 < KT) {
            int nb = (kt + 1) & 1;
            *(uint4*)(&As[nb][ra0*20 + ca0]) = cvt4(pa0);
            *(uint4*)(&As[nb][ra1*20 + ca1]) = cvt4(pa1);
            *(uint4*)(&Bs[nb][ra0*20 + ca0]) = cvt4(pb0);
            *(uint4*)(&Bs[nb][ra1*20 + ca1]) = cvt4(pb1);
            __syncthreads();
        }
    }

    #pragma unroll
    for (int i = 0; i < 4; i++) {
        #pragma unroll
        for (int j = 0; j < 4; j++) {
            int row = m0 + wm + (i << 4) + g;
            int col = n0 + wn + (j << 3) + (tg << 1);
            float bx = 0.f, by = 0.f;
            if (bias) { bx = bias[col]; by = bias[col + 1]; }
            float2 v0 = make_float2(acc[i][j][0] + bx, acc[i][j][1] + by);
            float2 v1 = make_float2(acc[i][j][2] + bx, acc[i][j][3] + by);
            *(float2*)(C + (size_t)row * ldc + col)       = v0;
            *(float2*)(C + (size_t)(row + 8) * ldc + col) = v1;
        }
    }
}

// ===============================================================================
// scores: S[bh] = mask(Q K^T * scale) — same core, K=128, epilogue applies mask
// ===============================================================================
__global__ __launch_bounds__(256, 2)
void scores_mma(const float* __restrict__ Q, const float* __restrict__ Kc,
                const void* __restrict__ conn, float* __restrict__ S)
{
    int bh = blockIdx.z;
    int b = bh >> 2, h = bh & 3;
    const float* A  = Q  + (size_t)b * A_ * D_ + h * HD_;
    const float* Bm = Kc + (size_t)b * A_ * D_ + h * HD_;
    float* C = S + (size_t)bh * A_ * A_;
    size_t cbase = (size_t)b * A_ * A_;
    int fmt = g_connfmt;

    __shared__ uint32_t As[2][128*20];
    __shared__ uint32_t Bs[2][128*20];
    int t = threadIdx.x;
    int m0 = blockIdx.y << 7, n0 = blockIdx.x << 7;
    int warp = t >> 5, lane = t & 31, g = lane >> 2, tg = lane & 3;
    int wm = (warp & 1) << 6;
    int wn = (warp >> 1) << 5;
    float acc[4][4][4] = {};

    int ra0 = t >> 2,         ca0 = (t & 3) << 2;
    int ra1 = (t + 256) >> 2, ca1 = (t & 3) << 2;
    const float* Ap0 = A  + (size_t)(m0 + ra0) * D_ + ca0;
    const float* Ap1 = A  + (size_t)(m0 + ra1) * D_ + ca1;
    const float* Bp0 = Bm + (size_t)(n0 + ra0) * D_ + ca0;
    const float* Bp1 = Bm + (size_t)(n0 + ra1) * D_ + ca1;

    float4 pa0, pa1, pb0, pb1;
    const int KT = HD_ >> 4;   // 8

    pa0 = *(const float4*)(Ap0); pa1 = *(const float4*)(Ap1);
    pb0 = *(const float4*)(Bp0); pb1 = *(const float4*)(Bp1);
    *(uint4*)(&As[0][ra0*20 + ca0]) = cvt4(pa0);
    *(uint4*)(&As[0][ra1*20 + ca1]) = cvt4(pa1);
    *(uint4*)(&Bs[0][ra0*20 + ca0]) = cvt4(pb0);
    *(uint4*)(&Bs[0][ra1*20 + ca1]) = cvt4(pb1);
    __syncthreads();

    for (int kt = 0; kt < KT; kt++) {
        if (kt + 1 < KT) {
            int k0 = (kt + 1) << 4;
            pa0 = *(const float4*)(Ap0 + k0); pa1 = *(const float4*)(Ap1 + k0);
            pb0 = *(const float4*)(Bp0 + k0); pb1 = *(const float4*)(Bp1 + k0);
        }
        const uint32_t* as = As[kt & 1];
        const uint32_t* bs = Bs[kt & 1];
        #pragma unroll
        for (int ks = 0; ks < 2; ks++) {
            int kb = ks << 3;
            uint32_t af[4][4], bf[4][2];
            #pragma unroll
            for (int i = 0; i < 4; i++) {
                int r = wm + (i << 4) + g;
                af[i][0] = as[r*20 + kb + tg];
                af[i][1] = as[(r+8)*20 + kb + tg];
                af[i][2] = as[r*20 + kb + tg + 4];
                af[i][3] = as[(r+8)*20 + kb + tg + 4];
            }
            #pragma unroll
            for (int j = 0; j < 4; j++) {
                int n = wn + (j << 3) + g;
                bf[j][0] = bs[n*20 + kb + tg];
                bf[j][1] = bs[n*20 + kb + tg + 4];
            }
            #pragma unroll
            for (int i = 0; i < 4; i++)
                #pragma unroll
                for (int j = 0; j < 4; j++)
                    MMA8(acc[i][j], af[i], bf[j]);
        }
        if (kt + 1 < KT) {
            int nb = (kt + 1) & 1;
            *(uint4*)(&As[nb][ra0*20 + ca0]) = cvt4(pa0);
            *(uint4*)(&As[nb][ra1*20 + ca1]) = cvt4(pa1);
            *(uint4*)(&Bs[nb][ra0*20 + ca0]) = cvt4(pb0);
            *(uint4*)(&Bs[nb][ra1*20 + ca1]) = cvt4(pb1);
            __syncthreads();
        }
    }

    #pragma unroll
    for (int i = 0; i < 4; i++) {
        #pragma unroll
        for (int j = 0; j < 4; j++) {
            int row = m0 + wm + (i << 4) + g;
            int col = n0 + wn + (j << 3) + (tg << 1);
            size_t r0 = cbase + (size_t)row * A_ + col;
            size_t r1 = cbase + (size_t)(row + 8) * A_ + col;
            float2 v0, v1;
            v0.x = conn_at(conn, r0,     fmt) ? acc[i][j][0] * SCALE : -INFINITY;
            v0.y = conn_at(conn, r0 + 1, fmt) ? acc[i][j][1] * SCALE : -INFINITY;
            v1.x = conn_at(conn, r1,     fmt) ? acc[i][j][2] * SCALE : -INFINITY;
            v1.y = conn_at(conn, r1 + 1, fmt) ? acc[i][j][3] * SCALE : -INFINITY;
            *(float2*)(C + (size_t)row * A_ + col)       = v0;
            *(float2*)(C + (size_t)(row + 8) * A_ + col) = v1;
        }
    }
}

// ===============================================================================
// pv: O = P @ V  (NN GEMM). A = P [M=2048, K=2048], B = V' [K, N=128].
// Bs stored [k][n] with stride 136 (conflict-free).
// ===============================================================================
__global__ __launch_bounds__(256, 2)
void pv_mma(const float* __restrict__ S, const float* __restrict__ V,
            float* __restrict__ O)
{
    int bh = blockIdx.z;
    int b = bh >> 2, h = bh & 3;
    const float* A  = S + (size_t)bh * A_ * A_;             // lda = A_
    const float* Bm = V + (size_t)b * A_ * D_ + h * HD_;    // ldb = D_
    float* C        = O + (size_t)b * A_ * D_ + h * HD_;    // ldc = D_

    __shared__ uint32_t As[2][128*20];
    __shared__ uint32_t Bs[2][16*136];
    int t = threadIdx.x;
    int m0 = blockIdx.y << 7;
    const int n0 = 0;
    int warp = t >> 5, lane = t & 31, g = lane >> 2, tg = lane & 3;
    int wm = (warp & 1) << 6;
    int wn = (warp >> 1) << 5;
    float acc[4][4][4] = {};

    int ra0 = t >> 2,         ca0 = (t & 3) << 2;    // A loader
    int ra1 = (t + 256) >> 2, ca1 = (t & 3) << 2;
    int rb0 = t >> 5,         cb0 = (t & 31) << 2;   // B loader [16][128]
    int rb1 = (t + 256) >> 5, cb1 = (t & 31) << 2;
    const float* Ap0 = A + (size_t)(m0 + ra0) * A_ + ca0;
    const float* Ap1 = A + (size_t)(m0 + ra1) * A_ + ca1;

    float4 pa0, pa1, pb0, pb1;
    const int KT = A_ >> 4;   // 128

    pa0 = *(const float4*)(Ap0); pa1 = *(const float4*)(Ap1);
    pb0 = *(const float4*)(Bm + (size_t)rb0 * D_ + n0 + cb0);
    pb1 = *(const float4*)(Bm + (size_t)rb1 * D_ + n0 + cb1);
    *(uint4*)(&As[0][ra0*20 + ca0]) = cvt4(pa0);
    *(uint4*)(&As[0][ra1*20 + ca1]) = cvt4(pa1);
    *(uint4*)(&Bs[0][rb0*136 + cb0]) = cvt4(pb0);
    *(uint4*)(&Bs[0][rb1*136 + cb1]) = cvt4(pb1);
    __syncthreads();

    for (int kt = 0; kt < KT; kt++) {
        if (kt + 1 < KT) {
            int k0 = (kt + 1) << 4;
            pa0 = *(const float4*)(Ap0 + k0);
            pa1 = *(const float4*)(Ap1 + k0);
            pb0 = *(const float4*)(Bm + (size_t)(k0 + rb0) * D_ + n0 + cb0);
            pb1 = *(const float4*)(Bm + (size_t)(k0 + rb1) * D_ + n0 + cb1);
        }
        const uint32_t* as = As[kt & 1];
        const uint32_t* bs = Bs[kt & 1];
        #pragma unroll
        for (int ks = 0; ks < 2; ks++) {
            int kb = ks << 3;
            uint32_t af[4][4], bf[4][2];
            #pragma unroll
            for (int i = 0; i < 4; i++) {
                int r = wm + (i << 4) + g;
                af[i][0] = as[r*20 + kb + tg];
                af[i][1] = as[(r+8)*20 + kb + tg];
                af[i][2] = as[r*20 + kb + tg + 4];
                af[i][3] = as[(r+8)*20 + kb + tg + 4];
            }
            #pragma unroll
            for (int j = 0; j < 4; j++) {
                int n = wn + (j << 3) + g;
                bf[j][0] = bs[(kb + tg)*136 + n];
                bf[j][1] = bs[(kb + tg + 4)*136 + n];
            }
            #pragma unroll
            for (int i = 0; i < 4; i++)
                #pragma unroll
                for (int j = 0; j < 4; j++)
                    MMA8(acc[i][j], af[i], bf[j]);
        }
        if (kt + 1 < KT) {
            int nb = (kt + 1) & 1;
            *(uint4*)(&As[nb][ra0*20 + ca0]) = cvt4(pa0);
            *(uint4*)(&As[nb][ra1*20 + ca1]) = cvt4(pa1);
            *(uint4*)(&Bs[nb][rb0*136 + cb0]) = cvt4(pb0);
            *(uint4*)(&Bs[nb][rb1*136 + cb1]) = cvt4(pb1);
            __syncthreads();
        }
    }

    #pragma unroll
    for (int i = 0; i < 4; i++) {
        #pragma unroll
        for (int j = 0; j < 4; j++) {
            int row = m0 + wm + (i << 4) + g;
            int col = n0 + wn + (j << 3) + (tg << 1);
            *(float2*)(C + (size_t)row * D_ + col) =
                make_float2(acc[i][j][0], acc[i][j][1]);
            *(float2*)(C + (size_t)(row + 8) * D_ + col) =
                make_float2(acc[i][j][2], acc[i][j][3]);
        }
    }
}

// ---------------- softmax over rows of S (in place) ----------------------------
__global__ void softmax_kernel(float* __restrict__ S)
{
    __shared__ float redm[8];
    __shared__ float reds[8];
    float* p = S + (size_t)blockIdx.x * A_;
    int t = threadIdx.x;
    int warp = t >> 5, lane = t & 31;
    float4 v0 = ((float4*)p)[t];
    float4 v1 = ((float4*)p)[t + 256];
    float m = fmaxf(fmaxf(fmaxf(v0.x,v0.y),fmaxf(v0.z,v0.w)),
                    fmaxf(fmaxf(v1.x,v1.y),fmaxf(v1.z,v1.w)));
    #pragma unroll
    for (int o = 16; o; o >>= 1) m = fmaxf(m, __shfl_xor_sync(0xffffffffu, m, o));
    if (lane == 0) redm[warp] = m;
    __syncthreads();
    float mm = redm[0];
    #pragma unroll
    for (int i = 1; i < 8; i++) mm = fmaxf(mm, redm[i]);

    #define EX(x) ((x) <= -1e30f ? 0.f : __expf((x) - mm))
    v0.x = EX(v0.x); v0.y = EX(v0.y); v0.z = EX(v0.z); v0.w = EX(v0.w);
    v1.x = EX(v1.x); v1.y = EX(v1.y); v1.z = EX(v1.z); v1.w = EX(v1.w);
    #undef EX
    float s = v0.x+v0.y+v0.z+v0.w + v1.x+v1.y+v1.z+v1.w;
    #pragma unroll
    for (int o = 16; o; o >>= 1) s += __shfl_xor_sync(0xffffffffu, s, o);
    if (lane == 0) reds[warp] = s;
    __syncthreads();
    float tot = reds[0];
    #pragma unroll
    for (int i = 1; i < 8; i++) tot += reds[i];
    float inv = 1.f / tot;
    v0.x*=inv; v0.y*=inv; v0.z*=inv; v0.w*=inv;
    v1.x*=inv; v1.y*=inv; v1.z*=inv; v1.w*=inv;
    ((float4*)p)[t]       = v0;
    ((float4*)p)[t + 256] = v1;
}

// ---------------- launcher -----------------------------------------------------
extern "C" void kernel_launch(void* const* d_in, const int* in_sizes, int n_in,
                              void* d_out, int out_size)
{
    const float* x      = (const float*)d_in[0];
    const void*  conn   = (const void*)d_in[1];
    const float* Wq     = (const float*)d_in[2];
    const float* Wk     = (const float*)d_in[3];
    const float* Wv     = (const float*)d_in[4];
    const float* norm_w = (const float*)d_in[5];
    const float* norm_b = (const float*)d_in[6];
    const float* ln1_w  = (const float*)d_in[7];
    const float* ln1_b  = (const float*)d_in[8];
    const float* fc1_w  = (const float*)d_in[9];
    const float* fc1_b  = (const float*)d_in[10];
    const float* ln2_w  = (const float*)d_in[11];
    const float* ln2_b  = (const float*)d_in[12];
    const float* fc2_w  = (const float*)d_in[13];
    const float* fc2_b  = (const float*)d_in[14];
    float* out = (float*)d_out;

    float *p_xn, *p_q, *p_k, *p_v, *p_t1, *p_t2, *p_s;
    int* p_fmt;
    cudaGetSymbolAddress((void**)&p_xn, g_xn);
    cudaGetSymbolAddress((void**)&p_q,  g_q);
    cudaGetSymbolAddress((void**)&p_k,  g_k);
    cudaGetSymbolAddress((void**)&p_v,  g_v);
    cudaGetSymbolAddress((void**)&p_t1, g_t1);
    cudaGetSymbolAddress((void**)&p_t2, g_t2);
    cudaGetSymbolAddress((void**)&p_s,  g_s);
    cudaGetSymbolAddress((void**)&p_fmt, g_connfmt);

    cudaMemsetAsync(p_fmt, 0, sizeof(int));
    detect_kernel<<<256, 256>>>((const unsigned char*)conn);
    resolve_fmt_kernel<<<1, 1>>>();

    // 1. xn = LN(x)
    ln_kernel<false><<<M_, 128>>>(x, p_xn, norm_w, norm_b);

    // 2. Q, K, V (tf32 tensor cores)
    dim3 ggrid(D_/128, M_/128);   // (4, 64)
    mma_nt<<<ggrid, 256>>>(p_xn, D_, Wq, D_, p_q, D_, D_, nullptr);
    mma_nt<<<ggrid, 256>>>(p_xn, D_, Wk, D_, p_k, D_, D_, nullptr);
    mma_nt<<<ggrid, 256>>>(p_xn, D_, Wv, D_, p_v, D_, D_, nullptr);

    // 3. scores + mask
    scores_mma<<<dim3(A_/128, A_/128, NBH), 256>>>(p_q, p_k, conn, p_s);

    // 4. softmax
    softmax_kernel<<<NBH * A_, 256>>>(p_s);

    // 5. O = P @ V
    pv_mma<<<dim3(1, A_/128, NBH), 256>>>(p_s, p_v, p_xn);

    // 6. t1 = LN(swish(O)); h1 = t1 @ fc1^T + b1
    ln_kernel<true><<<M_, 128>>>(p_xn, p_t1, ln1_w, ln1_b);
    mma_nt<<<ggrid, 256>>>(p_t1, D_, fc1_w, D_, p_t2, D_, D_, fc1_b);

    // 7. t1 = LN(swish(h1)); h2 = t1 @ fc2^T + b2
    ln_kernel<true><<<M_, 128>>>(p_t2, p_t1, ln2_w, ln2_b);
    mma_nt<<<ggrid, 256>>>(p_t1, D_, fc2_w, D_, p_t2, D_, D_, fc2_b);

    // 8. out = LN(h2)
    ln_kernel<false><<<M_, 128>>>(p_t2, out, norm_w, norm_b);
}